// round 1
// baseline (speedup 1.0000x reference)
#include <cuda_runtime.h>
#include <math.h>

// Problem constants
#define NN 512          // nodes
#define BB 32           // batch
#define TT 12           // time
#define CC 64           // channels in/out
#define NPIECE 9        // non-identity (support,power) pieces
#define NJ (BB*TT*CC)   // 24576 columns of the big GEMM
#define KBIG (NPIECE*NN)// 4608
#define NPOS (BB*NN*TT) // 196608 positions

// ---------------- scratch (device globals; no allocation allowed) ----------------
__device__ float g_smW1[40*20];
__device__ float g_smW2[40*20];
__device__ float g_e1[NN*20];
__device__ float g_e2[NN*20];
__device__ float g_A[NN*NN];
__device__ float g_d[NN];
__device__ float g_S0[NN*NN];   // Ls
__device__ float g_S1[NN*NN];   // T2
__device__ float g_S2[NN*NN];   // T3
__device__ float g_P0[NN*NN];   // S^2 scratch
__device__ float g_P1[NN*NN];   // S^3 scratch
__device__ float g_ZT[(size_t)NN*KBIG];          // 512 x 4608, ZT[w][p*512+v] = Zp[v][w]
__device__ float g_Wcat[10*64*64];               // pieces 0..8 + Weff0 as piece 9
__device__ float g_U[(size_t)NPIECE*NN*NJ];      // 4608 x 24576  (~453 MB)
__device__ float g_H[(size_t)NN*NJ];             // 512 x 24576   (~50 MB)

// ---------------- tiny preprocessing kernels ----------------

// column softmax (axis=0, over 40 rows) of W1 and W2 (40x20 each)
__global__ void k_softmax(const float* __restrict__ W1, const float* __restrict__ W2) {
    int t = threadIdx.x;
    if (t >= 40) return;
    const float* W = (t < 20) ? W1 : W2;
    float* S = (t < 20) ? g_smW1 : g_smW2;
    int c = (t < 20) ? t : t - 20;
    float m = -1e30f;
    for (int r = 0; r < 40; r++) m = fmaxf(m, W[r*20 + c]);
    float e[40];
    float s = 0.f;
    for (int r = 0; r < 40; r++) { e[r] = expf(W[r*20 + c] - m); s += e[r]; }
    float inv = 1.f / s;
    for (int r = 0; r < 40; r++) S[r*20 + c] = e[r] * inv;
}

// e1 = emb @ smW1, e2 = emb @ smW2, row-normalized
__global__ void k_embed(const float* __restrict__ emb) {
    int i = blockIdx.x;
    __shared__ float es[40];
    __shared__ float r1[20], r2[20], nrm[2];
    int tid = threadIdx.x;
    if (tid < 40) es[tid] = emb[i*40 + tid];
    __syncthreads();
    if (tid < 20) {
        float s = 0.f;
        for (int q = 0; q < 40; q++) s += es[q] * g_smW1[q*20 + tid];
        r1[tid] = s;
    } else if (tid < 40) {
        int c = tid - 20;
        float s = 0.f;
        for (int q = 0; q < 40; q++) s += es[q] * g_smW2[q*20 + c];
        r2[c] = s;
    }
    __syncthreads();
    if (tid < 2) {
        const float* rr = tid ? r2 : r1;
        float s = 0.f;
        for (int q = 0; q < 20; q++) s += rr[q]*rr[q];
        nrm[tid] = sqrtf(s) + 1e-8f;
    }
    __syncthreads();
    if (tid < 20)      g_e1[i*20 + tid]       = r1[tid]      / nrm[0];
    else if (tid < 40) g_e2[i*20 + (tid-20)]  = r2[tid-20]   / nrm[1];
}

// A = where(adj>0, e1_i.e2_j + adj, 9e-15); d = 1/sqrt(rowsum(A))
__global__ void k_buildA(const float* __restrict__ adj) {
    int i = blockIdx.x;
    __shared__ float e1s[20];
    __shared__ float red[256];
    int tid = threadIdx.x;
    if (tid < 20) e1s[tid] = g_e1[i*20 + tid];
    __syncthreads();
    float rs = 0.f;
    for (int j = tid; j < NN; j += 256) {
        float dot = 0.f;
        #pragma unroll
        for (int q = 0; q < 20; q++) dot += e1s[q] * g_e2[j*20 + q];
        float ad = adj[i*NN + j];
        float a = (ad > 0.f) ? (dot + ad) : 9e-15f;
        g_A[i*NN + j] = a;
        rs += a;
    }
    red[tid] = rs; __syncthreads();
    for (int s = 128; s > 0; s >>= 1) {
        if (tid < s) red[tid] += red[tid + s];
        __syncthreads();
    }
    if (tid == 0) g_d[i] = 1.f / sqrtf(red[0]);
}

// Ls = -(d_i * A_ij * d_j)
__global__ void k_ls() {
    int i = blockIdx.x;
    float di = g_d[i];
    for (int j = threadIdx.x; j < NN; j += 256)
        g_S0[i*NN + j] = -(di * g_A[i*NN + j] * g_d[j]);
}

// generic 512x512 sgemm: C = alpha*A@B + beta*D  (D may be nullptr; identD -> D = I)
__global__ void __launch_bounds__(256) k_gemm512(const float* __restrict__ A, const float* __restrict__ B,
                                                 float* __restrict__ C, float alpha,
                                                 const float* __restrict__ D, float beta, int identD) {
    __shared__ float As[32][33];
    __shared__ float Bs[32][33];
    int row0 = blockIdx.y * 32, col0 = blockIdx.x * 32;
    int tid = threadIdx.x;
    int tx = tid & 15, ty = tid >> 4;
    float acc[2][2] = {};
    for (int k0 = 0; k0 < NN; k0 += 32) {
        #pragma unroll
        for (int l = 0; l < 4; l++) {
            int idx = tid + l*256;
            int r = idx >> 5, c = idx & 31;
            As[r][c] = A[(row0 + r)*NN + k0 + c];
            Bs[r][c] = B[(k0 + r)*NN + col0 + c];
        }
        __syncthreads();
        #pragma unroll
        for (int kk = 0; kk < 32; kk++) {
            #pragma unroll
            for (int a2 = 0; a2 < 2; a2++)
                #pragma unroll
                for (int b2 = 0; b2 < 2; b2++)
                    acc[a2][b2] = fmaf(As[ty + 16*a2][kk], Bs[kk][tx + 16*b2], acc[a2][b2]);
        }
        __syncthreads();
    }
    #pragma unroll
    for (int a2 = 0; a2 < 2; a2++)
        #pragma unroll
        for (int b2 = 0; b2 < 2; b2++) {
            int i = row0 + ty + 16*a2, j = col0 + tx + 16*b2;
            float extra = 0.f;
            if (identD)      extra = beta * ((i == j) ? 1.f : 0.f);
            else if (D)      extra = beta * D[i*NN + j];
            C[i*NN + j] = alpha * acc[a2][b2] + extra;
        }
}

// pack piece p: ZT[w][p*512+v] = src[v][w]
__global__ void k_packZ(const float* __restrict__ src, int p) {
    int w = blockIdx.x;
    int v = threadIdx.x;
    g_ZT[(size_t)w*KBIG + p*NN + v] = src[v*NN + w];
}

// pack channel-mix weights: pieces 0..8 = mlp_w blocks 4..12; piece 9 = sum of blocks 0..3
__global__ void k_packW(const float* __restrict__ mlp_w) {
    int p = blockIdx.x;
    for (int idx = threadIdx.x; idx < 4096; idx += blockDim.x) {
        int o = idx >> 6, c = idx & 63;
        float v;
        if (p < 9) v = mlp_w[o*832 + 256 + p*64 + c];
        else       v = mlp_w[o*832 + c] + mlp_w[o*832 + 64 + c]
                     + mlp_w[o*832 + 128 + c] + mlp_w[o*832 + 192 + c];
        g_Wcat[p*4096 + idx] = v;
    }
}

// ---------------- stage 1: channel-mix x by all 10 W pieces ----------------
// U[p*512+v][ (b*T+t)*64 + o ] = sum_c Wp[o][c] * x[b][v][t][c];  piece 9 -> g_H
__global__ void __launch_bounds__(256) k_stage1(const float* __restrict__ x) {
    __shared__ float Xs[64][68];   // [c][r]
    __shared__ float Ws[64][68];   // [c][o]
    int p = blockIdx.y;
    int r0 = blockIdx.x * 64;      // position tile
    int tid = threadIdx.x;
    const float* xt = x + (size_t)r0 * 64;
    #pragma unroll
    for (int l = 0; l < 4; l++) {
        int v = tid + l*256;
        int r = v >> 4;
        int cv = (v & 15) << 2;
        float4 a = *(const float4*)(xt + r*64 + cv);
        Xs[cv+0][r] = a.x; Xs[cv+1][r] = a.y; Xs[cv+2][r] = a.z; Xs[cv+3][r] = a.w;
    }
    const float* wt = g_Wcat + p*4096;
    #pragma unroll
    for (int l = 0; l < 4; l++) {
        int v = tid + l*256;
        int o = v >> 4;
        int cv = (v & 15) << 2;
        float4 a = *(const float4*)(wt + o*64 + cv);
        Ws[cv+0][o] = a.x; Ws[cv+1][o] = a.y; Ws[cv+2][o] = a.z; Ws[cv+3][o] = a.w;
    }
    __syncthreads();
    int tx = tid & 15, ty = tid >> 4;
    float acc[4][4] = {};
    #pragma unroll
    for (int c = 0; c < 64; c++) {
        float4 a = *(const float4*)&Xs[c][ty*4];
        float4 b = *(const float4*)&Ws[c][tx*4];
        float av[4] = {a.x, a.y, a.z, a.w};
        float bv[4] = {b.x, b.y, b.z, b.w};
        #pragma unroll
        for (int i = 0; i < 4; i++)
            #pragma unroll
            for (int j = 0; j < 4; j++)
                acc[i][j] = fmaf(av[i], bv[j], acc[i][j]);
    }
    #pragma unroll
    for (int i = 0; i < 4; i++) {
        int r = r0 + ty*4 + i;          // global position = (b*512+v)*12 + t
        int t = r % 12;
        int bv = r / 12;
        int v = bv & (NN - 1);
        int b = bv >> 9;
        int j = (b*TT + t)*64 + tx*4;
        float4 val = make_float4(acc[i][0], acc[i][1], acc[i][2], acc[i][3]);
        if (p < NPIECE)
            *(float4*)(g_U + (size_t)(p*NN + v)*NJ + j) = val;
        else
            *(float4*)(g_H + (size_t)v*NJ + j) = val;
    }
}

// ---------------- stage 3: H(512 x 24576) += ZT(512 x 4608) @ U(4608 x 24576) ----------------
// epilogue: out[b,w,t,o] = relu(acc + H + bias + x)
__global__ void __launch_bounds__(256) k_stage3(const float* __restrict__ x,
                                                const float* __restrict__ bias,
                                                float* __restrict__ out) {
    __shared__ float As[16][132];   // [k][m]
    __shared__ float Bs[16][132];   // [k][n]
    int rowBase = blockIdx.y * 128;
    int colBase = blockIdx.x * 128;
    int tid = threadIdx.x;
    int tx = tid & 15, ty = tid >> 4;
    float acc[8][8] = {};
    for (int k0 = 0; k0 < KBIG; k0 += 16) {
        #pragma unroll
        for (int l = 0; l < 2; l++) {
            int v = tid + l*256;
            int r = v >> 2;
            int kv = (v & 3) << 2;
            float4 a = *(const float4*)(g_ZT + (size_t)(rowBase + r)*KBIG + k0 + kv);
            As[kv+0][r] = a.x; As[kv+1][r] = a.y; As[kv+2][r] = a.z; As[kv+3][r] = a.w;
        }
        #pragma unroll
        for (int l = 0; l < 2; l++) {
            int v = tid + l*256;
            int r = v >> 5;
            int cv = (v & 31) << 2;
            *(float4*)&Bs[r][cv] = *(const float4*)(g_U + (size_t)(k0 + r)*NJ + colBase + cv);
        }
        __syncthreads();
        #pragma unroll
        for (int kk = 0; kk < 16; kk++) {
            float4 a0 = *(const float4*)&As[kk][ty*4];
            float4 a1 = *(const float4*)&As[kk][64 + ty*4];
            float4 b0 = *(const float4*)&Bs[kk][tx*4];
            float4 b1 = *(const float4*)&Bs[kk][64 + tx*4];
            float av[8] = {a0.x,a0.y,a0.z,a0.w, a1.x,a1.y,a1.z,a1.w};
            float bv[8] = {b0.x,b0.y,b0.z,b0.w, b1.x,b1.y,b1.z,b1.w};
            #pragma unroll
            for (int i = 0; i < 8; i++)
                #pragma unroll
                for (int j = 0; j < 8; j++)
                    acc[i][j] = fmaf(av[i], bv[j], acc[i][j]);
        }
        __syncthreads();
    }
    #pragma unroll
    for (int i = 0; i < 8; i++) {
        int w = rowBase + ((i < 4) ? (ty*4 + i) : (64 + ty*4 + i - 4));
        const float* Hrow = g_H + (size_t)w*NJ;
        #pragma unroll
        for (int j = 0; j < 8; j++) {
            int col = colBase + ((j < 4) ? (tx*4 + j) : (64 + tx*4 + j - 4));
            int o = col & 63;
            int bt = col >> 6;
            int b = bt / TT;
            int t = bt - b*TT;
            size_t addr = ((size_t)(b*NN + w)*TT + t)*64 + o;
            float val = acc[i][j] + Hrow[col] + bias[o] + x[addr];
            out[addr] = fmaxf(val, 0.f);
        }
    }
}

// ---------------- launch ----------------
extern "C" void kernel_launch(void* const* d_in, const int* in_sizes, int n_in,
                              void* d_out, int out_size) {
    (void)in_sizes; (void)n_in; (void)out_size;
    const float* x    = (const float*)d_in[0];
    const float* adj  = (const float*)d_in[1];
    const float* emb  = (const float*)d_in[2];
    const float* W1   = (const float*)d_in[3];
    const float* W2   = (const float*)d_in[4];
    const float* mlpw = (const float*)d_in[5];
    const float* mlpb = (const float*)d_in[6];
    float* out = (float*)d_out;

    float *pS0, *pS1, *pS2, *pP0, *pP1;
    cudaGetSymbolAddress((void**)&pS0, g_S0);
    cudaGetSymbolAddress((void**)&pS1, g_S1);
    cudaGetSymbolAddress((void**)&pS2, g_S2);
    cudaGetSymbolAddress((void**)&pP0, g_P0);
    cudaGetSymbolAddress((void**)&pP1, g_P1);

    k_softmax<<<1, 64>>>(W1, W2);
    k_embed<<<512, 64>>>(emb);
    k_buildA<<<512, 256>>>(adj);
    k_ls<<<512, 256>>>();

    dim3 g16(16, 16);
    // T2 = 2*Ls@Ls - I ; T3 = 2*Ls@T2 - Ls
    k_gemm512<<<g16, 256>>>(pS0, pS0, pS1, 2.f, nullptr, -1.f, 1);
    k_gemm512<<<g16, 256>>>(pS0, pS1, pS2, 2.f, pS0, -1.f, 0);

    const float* Ss[3] = {pS0, pS1, pS2};
    for (int s = 0; s < 3; s++) {
        k_gemm512<<<g16, 256>>>(Ss[s], Ss[s], pP0, 1.f, nullptr, 0.f, 0);  // S^2
        k_gemm512<<<g16, 256>>>(Ss[s], pP0, pP1, 1.f, nullptr, 0.f, 0);    // S^3
        k_packZ<<<512, 512>>>(Ss[s], s*3 + 0);
        k_packZ<<<512, 512>>>(pP0,   s*3 + 1);
        k_packZ<<<512, 512>>>(pP1,   s*3 + 2);
    }
    k_packW<<<10, 256>>>(mlpw);

    k_stage1<<<dim3(NPOS/64, 10), 256>>>(x);
    k_stage3<<<dim3(NJ/128, NN/128), 256>>>(x, mlpb, out);
}

// round 2
// speedup vs baseline: 2.3125x; 2.3125x over previous
#include <cuda_runtime.h>
#include <math.h>

#define NN 512
#define BB 32
#define TT 12
#define CC 64
#define NPIECE 9
#define NJ (BB*TT*CC)    // 24576
#define KBIG (NPIECE*NN) // 4608
#define NPOS (BB*NN*TT)  // 196608

// ---------------- device scratch ----------------
__device__ float g_smW1[40*20];
__device__ float g_smW2[40*20];
__device__ float g_e1[NN*20];
__device__ float g_e2[NN*20];
__device__ float g_A[NN*NN];
__device__ float g_d[NN];
__device__ float g_ZA[(size_t)NPIECE*NN*NN];   // stacked supports, k-major: [p*512+v][w]
__device__ float g_WT[64*640];                 // W^T: [c][p*64+o]
__device__ float g_U[(size_t)KBIG*NJ];         // 4608 x 24576
__device__ float g_H[(size_t)NN*NJ];           // 512 x 24576

// ---------------- helpers ----------------
__device__ __forceinline__ unsigned f2tf(float f) {
    unsigned u;
    asm("cvt.rna.tf32.f32 %0, %1;" : "=r"(u) : "f"(f));
    return u;
}

__device__ __forceinline__ void mma_tf32(float c[4], const unsigned a[4], const unsigned b[2]) {
    asm volatile("mma.sync.aligned.m16n8k8.row.col.f32.tf32.tf32.f32 "
        "{%0,%1,%2,%3}, {%4,%5,%6,%7}, {%8,%9}, {%0,%1,%2,%3};"
        : "+f"(c[0]), "+f"(c[1]), "+f"(c[2]), "+f"(c[3])
        : "r"(a[0]), "r"(a[1]), "r"(a[2]), "r"(a[3]), "r"(b[0]), "r"(b[1]));
}

// ---------------- preprocessing ----------------
__global__ void k_softmax(const float* __restrict__ W1, const float* __restrict__ W2) {
    int t = threadIdx.x;
    if (t >= 40) return;
    const float* W = (t < 20) ? W1 : W2;
    float* S = (t < 20) ? g_smW1 : g_smW2;
    int c = (t < 20) ? t : t - 20;
    float m = -1e30f;
    for (int r = 0; r < 40; r++) m = fmaxf(m, W[r*20 + c]);
    float e[40];
    float s = 0.f;
    for (int r = 0; r < 40; r++) { e[r] = expf(W[r*20 + c] - m); s += e[r]; }
    float inv = 1.f / s;
    for (int r = 0; r < 40; r++) S[r*20 + c] = e[r] * inv;
}

__global__ void k_embed(const float* __restrict__ emb) {
    int i = blockIdx.x;
    __shared__ float es[40];
    __shared__ float r1[20], r2[20], nrm[2];
    int tid = threadIdx.x;
    if (tid < 40) es[tid] = emb[i*40 + tid];
    __syncthreads();
    if (tid < 20) {
        float s = 0.f;
        for (int q = 0; q < 40; q++) s += es[q] * g_smW1[q*20 + tid];
        r1[tid] = s;
    } else if (tid < 40) {
        int c = tid - 20;
        float s = 0.f;
        for (int q = 0; q < 40; q++) s += es[q] * g_smW2[q*20 + c];
        r2[c] = s;
    }
    __syncthreads();
    if (tid < 2) {
        const float* rr = tid ? r2 : r1;
        float s = 0.f;
        for (int q = 0; q < 20; q++) s += rr[q]*rr[q];
        nrm[tid] = sqrtf(s) + 1e-8f;
    }
    __syncthreads();
    if (tid < 20)      g_e1[i*20 + tid]       = r1[tid]      / nrm[0];
    else if (tid < 40) g_e2[i*20 + (tid-20)]  = r2[tid-20]   / nrm[1];
}

__global__ void k_buildA(const float* __restrict__ adj) {
    int i = blockIdx.x;
    __shared__ float e1s[20];
    __shared__ float red[256];
    int tid = threadIdx.x;
    if (tid < 20) e1s[tid] = g_e1[i*20 + tid];
    __syncthreads();
    float rs = 0.f;
    for (int j = tid; j < NN; j += 256) {
        float dot = 0.f;
        #pragma unroll
        for (int q = 0; q < 20; q++) dot += e1s[q] * g_e2[j*20 + q];
        float ad = adj[i*NN + j];
        float a = (ad > 0.f) ? (dot + ad) : 9e-15f;
        g_A[i*NN + j] = a;
        rs += a;
    }
    red[tid] = rs; __syncthreads();
    for (int s = 128; s > 0; s >>= 1) {
        if (tid < s) red[tid] += red[tid + s];
        __syncthreads();
    }
    if (tid == 0) g_d[i] = 1.f / sqrtf(red[0]);
}

// Ls into g_ZA slot 0
__global__ void k_ls(float* __restrict__ out) {
    int i = blockIdx.x;
    float di = g_d[i];
    for (int j = threadIdx.x; j < NN; j += 256)
        out[i*NN + j] = -(di * g_A[i*NN + j] * g_d[j]);
}

// 512x512 sgemm: C = alpha*A@B + beta*D  (identD -> D = I)
__global__ void __launch_bounds__(256) k_gemm512(const float* __restrict__ A, const float* __restrict__ B,
                                                 float* __restrict__ C, float alpha,
                                                 const float* __restrict__ D, float beta, int identD) {
    __shared__ float As[32][33];
    __shared__ float Bs[32][33];
    int row0 = blockIdx.y * 32, col0 = blockIdx.x * 32;
    int tid = threadIdx.x;
    int tx = tid & 15, ty = tid >> 4;
    float acc[2][2] = {};
    for (int k0 = 0; k0 < NN; k0 += 32) {
        #pragma unroll
        for (int l = 0; l < 4; l++) {
            int idx = tid + l*256;
            int r = idx >> 5, c = idx & 31;
            As[r][c] = A[(row0 + r)*NN + k0 + c];
            Bs[r][c] = B[(k0 + r)*NN + col0 + c];
        }
        __syncthreads();
        #pragma unroll
        for (int kk = 0; kk < 32; kk++) {
            #pragma unroll
            for (int a2 = 0; a2 < 2; a2++)
                #pragma unroll
                for (int b2 = 0; b2 < 2; b2++)
                    acc[a2][b2] = fmaf(As[ty + 16*a2][kk], Bs[kk][tx + 16*b2], acc[a2][b2]);
        }
        __syncthreads();
    }
    #pragma unroll
    for (int a2 = 0; a2 < 2; a2++)
        #pragma unroll
        for (int b2 = 0; b2 < 2; b2++) {
            int i = row0 + ty + 16*a2, j = col0 + tx + 16*b2;
            float extra = 0.f;
            if (identD)      extra = beta * ((i == j) ? 1.f : 0.f);
            else if (D)      extra = beta * D[i*NN + j];
            C[i*NN + j] = alpha * acc[a2][b2] + extra;
        }
}

// W^T pack: g_WT[c][p*64+o]; pieces 0..8 = mlp blocks 4..12, piece 9 = sum of blocks 0..3
__global__ void k_packWT(const float* __restrict__ mlp_w) {
    int c = blockIdx.x;          // 0..63
    int n = threadIdx.x;         // 0..639
    int p = n >> 6, o = n & 63;
    float v;
    if (p < 9) v = mlp_w[o*832 + 256 + p*64 + c];
    else       v = mlp_w[o*832 + c] + mlp_w[o*832 + 64 + c]
                 + mlp_w[o*832 + 128 + c] + mlp_w[o*832 + 192 + c];
    g_WT[c*640 + n] = v;
}

// ---------------- stage 1 (tensor core): U/H = X @ W^T ----------------
// X: (196608 x 64) row-major. B = g_WT (64 x 640). BM=128, BN=128, whole K=64.
__global__ void __launch_bounds__(256) k_stage1_tc(const float* __restrict__ x) {
    extern __shared__ char smem[];
    unsigned* As = (unsigned*)smem;               // [128][68] m-major
    unsigned* Bs = As + 128*68;                   // [64][136] k-major
    float*    Cs = (float*)smem;                  // [128][132] (reuses As/Bs)

    const int tid = threadIdx.x;
    const int wid = tid >> 5, lane = tid & 31;
    const int qr = lane >> 2, qc = lane & 3;
    const int warpM = (wid >> 2) * 64;            // 0 or 64
    const int warpN = (wid & 3) * 32;             // 0,32,64,96
    const int r0 = blockIdx.y * 128;
    const int n0 = blockIdx.x * 128;

    // load X tile 128x64
    {
        int kq = tid & 15, rowb = tid >> 4;
        #pragma unroll
        for (int l = 0; l < 8; l++) {
            int row = rowb + l*16;
            float4 v = *(const float4*)(x + (size_t)(r0 + row)*64 + kq*4);
            unsigned* d = &As[row*68 + kq*4];
            d[0]=f2tf(v.x); d[1]=f2tf(v.y); d[2]=f2tf(v.z); d[3]=f2tf(v.w);
        }
    }
    // load W tile 64x128
    {
        int n4 = tid & 31, crb = tid >> 5;
        #pragma unroll
        for (int l = 0; l < 8; l++) {
            int cr = crb + l*8;
            float4 v = *(const float4*)(g_WT + cr*640 + n0 + n4*4);
            unsigned* d = &Bs[cr*136 + n4*4];
            d[0]=f2tf(v.x); d[1]=f2tf(v.y); d[2]=f2tf(v.z); d[3]=f2tf(v.w);
        }
    }
    __syncthreads();

    float acc[4][4][4] = {};
    #pragma unroll
    for (int ks = 0; ks < 8; ks++) {
        int kb = ks*8;
        unsigned a[4][4], b[4][2];
        #pragma unroll
        for (int mf = 0; mf < 4; mf++) {
            int m = warpM + mf*16 + qr;
            a[mf][0] = As[m*68 + kb + qc];
            a[mf][1] = As[(m+8)*68 + kb + qc];
            a[mf][2] = As[m*68 + kb + qc + 4];
            a[mf][3] = As[(m+8)*68 + kb + qc + 4];
        }
        #pragma unroll
        for (int nf = 0; nf < 4; nf++) {
            int n = warpN + nf*8 + qr;
            b[nf][0] = Bs[(kb+qc)*136 + n];
            b[nf][1] = Bs[(kb+qc+4)*136 + n];
        }
        #pragma unroll
        for (int mf = 0; mf < 4; mf++)
            #pragma unroll
            for (int nf = 0; nf < 4; nf++)
                mma_tf32(acc[mf][nf], a[mf], b[nf]);
    }
    __syncthreads();

    // transpose through smem, then coalesced scatter
    #pragma unroll
    for (int mf = 0; mf < 4; mf++)
        #pragma unroll
        for (int nf = 0; nf < 4; nf++) {
            float* C0 = &Cs[(warpM + mf*16 + qr)*132 + warpN + nf*8 + qc*2];
            C0[0] = acc[mf][nf][0]; C0[1] = acc[mf][nf][1];
            C0[132*8] = acc[mf][nf][2]; C0[132*8+1] = acc[mf][nf][3];
        }
    __syncthreads();

    #pragma unroll
    for (int pass = 0; pass < 16; pass++) {
        int idx = tid + pass*256;        // 4096 quads
        int row = idx >> 5, n4 = idx & 31;
        int r = r0 + row;
        int b = r / 6144; int rem = r - b*6144;
        int v = rem / 12; int t = rem - v*12;
        int nloc = n4*4;
        int n = n0 + nloc;
        int p = n >> 6, o = n & 63;
        float4 c = *(float4*)&Cs[row*132 + nloc];
        size_t j = (size_t)(b*12 + t)*64 + o;
        if (p < 9) *(float4*)(g_U + (size_t)(p*512 + v)*NJ + j) = c;
        else       *(float4*)(g_H + (size_t)v*NJ + j) = c;
    }
}

// ---------------- stage 3 (tensor core): H += ZA^T-ish big GEMM + epilogue ----------------
// A = g_ZA (k-major: [k][w], 4608x512), B = g_U ([k][n], 4608x24576)
// C tile 256x128. 512 threads = 16 warps (4m x 4n), warp tile 64x32.
__global__ void __launch_bounds__(512) k_stage3_tc(const float* __restrict__ x,
                                                   const float* __restrict__ bias,
                                                   float* __restrict__ out) {
    extern __shared__ char smem[];
    unsigned* As = (unsigned*)smem;               // [32][264]
    unsigned* Bs = As + 32*264;                   // [32][136]
    float*    Cs = (float*)smem;                  // [128][132] (reuse)

    const int tid = threadIdx.x;
    const int wid = tid >> 5, lane = tid & 31;
    const int qr = lane >> 2, qc = lane & 3;
    const int warpM = (wid >> 2) * 64;            // 0,64,128,192
    const int warpN = (wid & 3) * 32;
    const int rowBase = blockIdx.y * 256;
    const int colBase = blockIdx.x * 128;

    float acc[4][4][4] = {};

    const int m4 = tid & 63, krbA = tid >> 6;
    const int n4 = tid & 31, krbB = tid >> 5;

    for (int k0 = 0; k0 < KBIG; k0 += 32) {
        #pragma unroll
        for (int l = 0; l < 4; l++) {
            int kr = krbA + l*8;
            float4 v = *(const float4*)(g_ZA + (size_t)(k0 + kr)*512 + rowBase + m4*4);
            unsigned* d = &As[kr*264 + m4*4];
            d[0]=f2tf(v.x); d[1]=f2tf(v.y); d[2]=f2tf(v.z); d[3]=f2tf(v.w);
        }
        #pragma unroll
        for (int l = 0; l < 2; l++) {
            int kr = krbB + l*16;
            float4 v = *(const float4*)(g_U + (size_t)(k0 + kr)*NJ + colBase + n4*4);
            unsigned* d = &Bs[kr*136 + n4*4];
            d[0]=f2tf(v.x); d[1]=f2tf(v.y); d[2]=f2tf(v.z); d[3]=f2tf(v.w);
        }
        __syncthreads();
        #pragma unroll
        for (int kk = 0; kk < 4; kk++) {
            int kb = kk*8;
            unsigned a[4][4], b[4][2];
            #pragma unroll
            for (int mf = 0; mf < 4; mf++) {
                const unsigned* A0 = &As[(kb+qc)*264 + warpM + mf*16 + qr];
                const unsigned* A1 = &As[(kb+qc+4)*264 + warpM + mf*16 + qr];
                a[mf][0] = A0[0]; a[mf][1] = A0[8];
                a[mf][2] = A1[0]; a[mf][3] = A1[8];
            }
            #pragma unroll
            for (int nf = 0; nf < 4; nf++) {
                int n = warpN + nf*8 + qr;
                b[nf][0] = Bs[(kb+qc)*136 + n];
                b[nf][1] = Bs[(kb+qc+4)*136 + n];
            }
            #pragma unroll
            for (int mf = 0; mf < 4; mf++)
                #pragma unroll
                for (int nf = 0; nf < 4; nf++)
                    mma_tf32(acc[mf][nf], a[mf], b[nf]);
        }
        __syncthreads();
    }

    // epilogue in two 128-row halves through smem
    #pragma unroll
    for (int h = 0; h < 2; h++) {
        __syncthreads();
        if ((wid >> 3) == h) {
            int mbase = warpM - h*128;
            #pragma unroll
            for (int mf = 0; mf < 4; mf++)
                #pragma unroll
                for (int nf = 0; nf < 4; nf++) {
                    float* C0 = &Cs[(mbase + mf*16 + qr)*132 + warpN + nf*8 + qc*2];
                    C0[0] = acc[mf][nf][0]; C0[1] = acc[mf][nf][1];
                    C0[132*8] = acc[mf][nf][2]; C0[132*8+1] = acc[mf][nf][3];
                }
        }
        __syncthreads();
        #pragma unroll
        for (int pass = 0; pass < 8; pass++) {
            int idx = tid + pass*512;      // 4096 quads
            int row = idx >> 5, nq = idx & 31;
            int w = rowBase + h*128 + row;
            int col = colBase + nq*4;
            int o = col & 63, bt = col >> 6;
            int b = bt / 12, t = bt - b*12;
            size_t addr = ((size_t)(b*512 + w)*12 + t)*64 + o;
            float4 c  = *(float4*)&Cs[row*132 + nq*4];
            float4 hv = *(const float4*)(g_H + (size_t)w*NJ + col);
            float4 bi = *(const float4*)(bias + o);
            float4 xr = *(const float4*)(x + addr);
            float4 r;
            r.x = fmaxf(c.x + hv.x + bi.x + xr.x, 0.f);
            r.y = fmaxf(c.y + hv.y + bi.y + xr.y, 0.f);
            r.z = fmaxf(c.z + hv.z + bi.z + xr.z, 0.f);
            r.w = fmaxf(c.w + hv.w + bi.w + xr.w, 0.f);
            *(float4*)(out + addr) = r;
        }
    }
}

// ---------------- launch ----------------
extern "C" void kernel_launch(void* const* d_in, const int* in_sizes, int n_in,
                              void* d_out, int out_size) {
    (void)in_sizes; (void)n_in; (void)out_size;
    const float* x    = (const float*)d_in[0];
    const float* adj  = (const float*)d_in[1];
    const float* emb  = (const float*)d_in[2];
    const float* W1   = (const float*)d_in[3];
    const float* W2   = (const float*)d_in[4];
    const float* mlpw = (const float*)d_in[5];
    const float* mlpb = (const float*)d_in[6];
    float* out = (float*)d_out;

    float* za;
    cudaGetSymbolAddress((void**)&za, g_ZA);
    float* S[9];
    for (int p = 0; p < 9; p++) S[p] = za + (size_t)p * NN * NN;

    static int configured = 0;
    if (!configured) {
        cudaFuncSetAttribute(k_stage1_tc, cudaFuncAttributeMaxDynamicSharedMemorySize, 70000);
        cudaFuncSetAttribute(k_stage3_tc, cudaFuncAttributeMaxDynamicSharedMemorySize, 70000);
        configured = 1;
    }

    k_softmax<<<1, 64>>>(W1, W2);
    k_embed<<<512, 64>>>(emb);
    k_buildA<<<512, 256>>>(adj);
    k_ls<<<512, 256>>>(S[0]);

    dim3 g16(16, 16);
    // slots: 0 Ls, 1 Ls^2, 2 Ls^3, 3 T2, 4 T2^2, 5 T2^3, 6 T3, 7 T3^2, 8 T3^3
    k_gemm512<<<g16, 256>>>(S[0], S[0], S[3], 2.f, nullptr, -1.f, 1);   // T2 = 2Ls^2 - I
    k_gemm512<<<g16, 256>>>(S[0], S[3], S[6], 2.f, S[0], -1.f, 0);      // T3 = 2Ls T2 - Ls
    k_gemm512<<<g16, 256>>>(S[0], S[0], S[1], 1.f, nullptr, 0.f, 0);    // Ls^2
    k_gemm512<<<g16, 256>>>(S[0], S[1], S[2], 1.f, nullptr, 0.f, 0);    // Ls^3
    k_gemm512<<<g16, 256>>>(S[3], S[3], S[4], 1.f, nullptr, 0.f, 0);    // T2^2
    k_gemm512<<<g16, 256>>>(S[3], S[4], S[5], 1.f, nullptr, 0.f, 0);    // T2^3
    k_gemm512<<<g16, 256>>>(S[6], S[6], S[7], 1.f, nullptr, 0.f, 0);    // T3^2
    k_gemm512<<<g16, 256>>>(S[6], S[7], S[8], 1.f, nullptr, 0.f, 0);    // T3^3

    k_packWT<<<64, 640>>>(mlpw);

    k_stage1_tc<<<dim3(5, NPOS/128), 256, 70000>>>(x);
    k_stage3_tc<<<dim3(NJ/128, NN/256), 512, 70000>>>(x, mlpb, out);
}

// round 4
// speedup vs baseline: 5.2555x; 2.2727x over previous
#include <cuda_runtime.h>
#include <cuda_fp16.h>
#include <math.h>

#define NN 512
#define BB 32
#define TT 12
#define CC 64
#define NPIECE 9
#define NJ (BB*TT*CC)    // 24576
#define NPOS (BB*NN*TT)  // 196608

// ---------------- device scratch ----------------
__device__ float g_smW1[40*20];
__device__ float g_smW2[40*20];
__device__ float g_e1[NN*20];
__device__ float g_e2[NN*20];
__device__ float g_A[NN*NN];
__device__ float g_d[NN];
__device__ float  g_ZA[(size_t)NPIECE*NN*NN];   // supports fp32, k-major: [p*512+v][w]
__device__ __half g_Zh[(size_t)NPIECE*NN*NN];   // fp16 copy
__device__ __half g_xh[(size_t)NN*NJ];          // x transposed: [v][(b*12+t)*64+c]
__device__ __half g_Wh[10*64*64];               // [p][c][o]; p=9 is identity-piece weight

// ---------------- helpers ----------------
__device__ __forceinline__ unsigned f2tf(float f) {
    unsigned u;
    asm("cvt.rna.tf32.f32 %0, %1;" : "=r"(u) : "f"(f));
    return u;
}
__device__ __forceinline__ void mma_tf32(float c[4], const unsigned a[4], const unsigned b[2]) {
    asm volatile("mma.sync.aligned.m16n8k8.row.col.f32.tf32.tf32.f32 "
        "{%0,%1,%2,%3}, {%4,%5,%6,%7}, {%8,%9}, {%0,%1,%2,%3};"
        : "+f"(c[0]), "+f"(c[1]), "+f"(c[2]), "+f"(c[3])
        : "r"(a[0]), "r"(a[1]), "r"(a[2]), "r"(a[3]), "r"(b[0]), "r"(b[1]));
}
__device__ __forceinline__ void mma_f16(float c[4], const unsigned a[4], const unsigned b[2]) {
    asm volatile("mma.sync.aligned.m16n8k16.row.col.f32.f16.f16.f32 "
        "{%0,%1,%2,%3}, {%4,%5,%6,%7}, {%8,%9}, {%0,%1,%2,%3};"
        : "+f"(c[0]), "+f"(c[1]), "+f"(c[2]), "+f"(c[3])
        : "r"(a[0]), "r"(a[1]), "r"(a[2]), "r"(a[3]), "r"(b[0]), "r"(b[1]));
}
__device__ __forceinline__ void ldm4t(unsigned r[4], const __half* p) {
    unsigned a = (unsigned)__cvta_generic_to_shared(p);
    asm volatile("ldmatrix.sync.aligned.m8n8.x4.trans.shared.b16 {%0,%1,%2,%3}, [%4];"
        : "=r"(r[0]), "=r"(r[1]), "=r"(r[2]), "=r"(r[3]) : "r"(a));
}
__device__ __forceinline__ void ldm4(unsigned r[4], const __half* p) {
    unsigned a = (unsigned)__cvta_generic_to_shared(p);
    asm volatile("ldmatrix.sync.aligned.m8n8.x4.shared.b16 {%0,%1,%2,%3}, [%4];"
        : "=r"(r[0]), "=r"(r[1]), "=r"(r[2]), "=r"(r[3]) : "r"(a));
}
__device__ __forceinline__ void cp16(const __half* smem_dst, const __half* gsrc) {
    unsigned sa = (unsigned)__cvta_generic_to_shared(smem_dst);
    asm volatile("cp.async.ca.shared.global [%0], [%1], 16;" :: "r"(sa), "l"(gsrc));
}
__device__ __forceinline__ void cp_commit() { asm volatile("cp.async.commit_group;"); }
__device__ __forceinline__ void cp_wait0() { asm volatile("cp.async.wait_group 0;"); }
__device__ __forceinline__ void cp_wait1() { asm volatile("cp.async.wait_group 1;"); }

// ---------------- preprocessing ----------------
__global__ void k_softmax(const float* __restrict__ W1, const float* __restrict__ W2) {
    int t = threadIdx.x;
    if (t >= 40) return;
    const float* W = (t < 20) ? W1 : W2;
    float* S = (t < 20) ? g_smW1 : g_smW2;
    int c = (t < 20) ? t : t - 20;
    float m = -1e30f;
    for (int r = 0; r < 40; r++) m = fmaxf(m, W[r*20 + c]);
    float e[40];
    float s = 0.f;
    for (int r = 0; r < 40; r++) { e[r] = expf(W[r*20 + c] - m); s += e[r]; }
    float inv = 1.f / s;
    for (int r = 0; r < 40; r++) S[r*20 + c] = e[r] * inv;
}

__global__ void k_embed(const float* __restrict__ emb) {
    int i = blockIdx.x;
    __shared__ float es[40];
    __shared__ float r1[20], r2[20], nrm[2];
    int tid = threadIdx.x;
    if (tid < 40) es[tid] = emb[i*40 + tid];
    __syncthreads();
    if (tid < 20) {
        float s = 0.f;
        for (int q = 0; q < 40; q++) s += es[q] * g_smW1[q*20 + tid];
        r1[tid] = s;
    } else if (tid < 40) {
        int c = tid - 20;
        float s = 0.f;
        for (int q = 0; q < 40; q++) s += es[q] * g_smW2[q*20 + c];
        r2[c] = s;
    }
    __syncthreads();
    if (tid < 2) {
        const float* rr = tid ? r2 : r1;
        float s = 0.f;
        for (int q = 0; q < 20; q++) s += rr[q]*rr[q];
        nrm[tid] = sqrtf(s) + 1e-8f;
    }
    __syncthreads();
    if (tid < 20)      g_e1[i*20 + tid]       = r1[tid]      / nrm[0];
    else if (tid < 40) g_e2[i*20 + (tid-20)]  = r2[tid-20]   / nrm[1];
}

__global__ void k_buildA(const float* __restrict__ adj) {
    int i = blockIdx.x;
    __shared__ float e1s[20];
    __shared__ float red[256];
    int tid = threadIdx.x;
    if (tid < 20) e1s[tid] = g_e1[i*20 + tid];
    __syncthreads();
    float rs = 0.f;
    for (int j = tid; j < NN; j += 256) {
        float dot = 0.f;
        #pragma unroll
        for (int q = 0; q < 20; q++) dot += e1s[q] * g_e2[j*20 + q];
        float ad = adj[i*NN + j];
        float a = (ad > 0.f) ? (dot + ad) : 9e-15f;
        g_A[i*NN + j] = a;
        rs += a;
    }
    red[tid] = rs; __syncthreads();
    for (int s = 128; s > 0; s >>= 1) {
        if (tid < s) red[tid] += red[tid + s];
        __syncthreads();
    }
    if (tid == 0) g_d[i] = 1.f / sqrtf(red[0]);
}

__global__ void k_ls(float* __restrict__ out) {
    int i = blockIdx.x;
    float di = g_d[i];
    for (int j = threadIdx.x; j < NN; j += 256)
        out[i*NN + j] = -(di * g_A[i*NN + j] * g_d[j]);
}

// 512^3 gemm on tensor cores (tf32): C = alpha*A@B + beta*(D or I)
__global__ void __launch_bounds__(256) k_gemm512_tc(const float* __restrict__ A, const float* __restrict__ B,
                                                    float* __restrict__ C, float alpha,
                                                    const float* __restrict__ D, float beta, int identD) {
    __shared__ unsigned As[64*36];   // m-major [m][k]
    __shared__ unsigned Bs[32*68];   // k-major [k][n]
    const int tid = threadIdx.x;
    const int wid = tid >> 5, lane = tid & 31;
    const int qr = lane >> 2, qc = lane & 3;
    const int warpM = (wid >> 2) * 32;
    const int warpN = (wid & 3) * 16;
    const int row0 = blockIdx.y * 64, col0 = blockIdx.x * 64;
    float acc[2][2][4] = {};
    for (int k0 = 0; k0 < 512; k0 += 32) {
        #pragma unroll
        for (int l = 0; l < 2; l++) {
            int idx = tid + l*256;
            int m = idx >> 3, k4 = (idx & 7) << 2;
            float4 v = *(const float4*)(A + (size_t)(row0 + m)*512 + k0 + k4);
            unsigned* d = &As[m*36 + k4];
            d[0]=f2tf(v.x); d[1]=f2tf(v.y); d[2]=f2tf(v.z); d[3]=f2tf(v.w);
        }
        #pragma unroll
        for (int l = 0; l < 2; l++) {
            int idx = tid + l*256;
            int kr = idx >> 4, n4 = (idx & 15) << 2;
            float4 v = *(const float4*)(B + (size_t)(k0 + kr)*512 + col0 + n4);
            unsigned* d = &Bs[kr*68 + n4];
            d[0]=f2tf(v.x); d[1]=f2tf(v.y); d[2]=f2tf(v.z); d[3]=f2tf(v.w);
        }
        __syncthreads();
        #pragma unroll
        for (int kk = 0; kk < 4; kk++) {
            int kb = kk*8;
            unsigned a[2][4], b[2][2];
            #pragma unroll
            for (int mf = 0; mf < 2; mf++) {
                int m = warpM + mf*16 + qr;
                a[mf][0] = As[m*36 + kb + qc];
                a[mf][1] = As[(m+8)*36 + kb + qc];
                a[mf][2] = As[m*36 + kb + qc + 4];
                a[mf][3] = As[(m+8)*36 + kb + qc + 4];
            }
            #pragma unroll
            for (int nf = 0; nf < 2; nf++) {
                int n = warpN + nf*8 + qr;
                b[nf][0] = Bs[(kb+qc)*68 + n];
                b[nf][1] = Bs[(kb+qc+4)*68 + n];
            }
            #pragma unroll
            for (int mf = 0; mf < 2; mf++)
                #pragma unroll
                for (int nf = 0; nf < 2; nf++)
                    mma_tf32(acc[mf][nf], a[mf], b[nf]);
        }
        __syncthreads();
    }
    #pragma unroll
    for (int mf = 0; mf < 2; mf++)
        #pragma unroll
        for (int nf = 0; nf < 2; nf++)
            #pragma unroll
            for (int e = 0; e < 4; e++) {
                int i = row0 + warpM + mf*16 + qr + (e >> 1)*8;
                int j = col0 + warpN + nf*8 + qc*2 + (e & 1);
                float extra = 0.f;
                if (identD)  extra = beta * ((i == j) ? 1.f : 0.f);
                else if (D)  extra = beta * D[i*512 + j];
                C[i*512 + j] = alpha * acc[mf][nf][e] + extra;
            }
}

// converts
__global__ void k_zh(const float* __restrict__ za) {
    int idx = blockIdx.x*256 + threadIdx.x;    // each handles 4
    float4 v = *(const float4*)(za + (size_t)idx*4);
    __half2 h0 = __floats2half2_rn(v.x, v.y), h1 = __floats2half2_rn(v.z, v.w);
    uint2 u; u.x = *(unsigned*)&h0; u.y = *(unsigned*)&h1;
    *(uint2*)(g_Zh + (size_t)idx*4) = u;
}

__global__ void k_xh(const float* __restrict__ x) {
    int b = blockIdx.x, v = blockIdx.y;
    int tc = threadIdx.x * 4;
    float4 f = *(const float4*)(x + ((size_t)(b*512 + v)*12)*64 + tc);
    __half2 h0 = __floats2half2_rn(f.x, f.y), h1 = __floats2half2_rn(f.z, f.w);
    uint2 u; u.x = *(unsigned*)&h0; u.y = *(unsigned*)&h1;
    *(uint2*)(g_xh + (size_t)v*NJ + b*768 + tc) = u;
}

__global__ void k_packWh(const float* __restrict__ mlp_w) {
    int idx = blockIdx.x*1024 + threadIdx.x;   // 40960 total
    int p = idx >> 12, rem = idx & 4095;
    int c = rem >> 6, o = rem & 63;
    float v;
    if (p < 9) v = mlp_w[o*832 + 256 + p*64 + c];
    else       v = mlp_w[o*832 + c] + mlp_w[o*832 + 64 + c]
                 + mlp_w[o*832 + 128 + c] + mlp_w[o*832 + 192 + c];
    g_Wh[idx] = __float2half(v);
}

// ---------------- fused main kernel ----------------
// Per 128x128 output tile (w-rows x (bt,o)-cols):
//   loop p in 0..8: G_p = Z_p^T @ x_r (K=512, fp16 mma) -> smem fp16 -> out += G_p @ W_p (K=64)
//   identity piece: G = x_r tile itself with Wh[9]
//   epilogue: relu(out + bias + x_residual)
__global__ void __launch_bounds__(256, 1) k_main(const float* __restrict__ x,
                                                 const float* __restrict__ bias,
                                                 float* __restrict__ out) {
    extern __shared__ __half sm[];
    __half* Ab0 = sm;                    // [64][136] x2
    __half* Bb0 = sm + 2*64*136;         // [64][136] x2
    __half* Gs  = sm + 4*64*136;         // [128][136]
    __half* Whs = Gs + 128*136;          // [10][64][72]
    float*  Cs  = (float*)sm;            // overlays Ab/Bb for epilogue (128x132 fp32)

    const int tid = threadIdx.x;
    const int wid = tid >> 5, lane = tid & 31;
    const int qr = lane >> 2, qc = lane & 3;
    const int warpM = (wid >> 2) * 64;        // 0,64
    const int warpN = (wid & 3) * 32;         // 0,32,64,96
    const int rowBase = blockIdx.y * 128;
    const int colBase = blockIdx.x * 128;

    const int g = lane >> 3, lrow = lane & 7;
    const int aTrow = (g >> 1)*8 + lrow, aTcol = (g & 1)*8;   // A trans groups
    const int bTrow = (g & 1)*8 + lrow, bTcol = (g >> 1)*8;   // B trans / G non-trans groups

    float acc[4][4][4] = {};
    float oacc[4][4][4] = {};

    // prefetch all W pieces (group 0)
    #pragma unroll
    for (int l = 0; l < 20; l++) {
        int idx = tid + l*256;              // 5120 tasks
        int p = idx >> 9; int rem = idx & 511;
        int c = rem >> 3, seg = rem & 7;
        cp16(&Whs[p*4608 + c*72 + seg*8], g_Wh + (size_t)(p*64 + c)*64 + seg*8);
    }
    // prefetch stage 0 (p=0, kc=0)
    #pragma unroll
    for (int l = 0; l < 4; l++) {
        int idx = tid + l*256;
        int kr = idx >> 4, seg = idx & 15;
        cp16(&Ab0[kr*136 + seg*8], g_Zh + (size_t)kr*512 + rowBase + seg*8);
        cp16(&Bb0[kr*136 + seg*8], g_xh + (size_t)kr*NJ + colBase + seg*8);
    }
    cp_commit();

    int buf = 0;
    for (int s = 0; s < 72; s++) {
        int kc = s & 7;
        if (s < 71) {
            int s1 = s + 1;
            int p1 = s1 >> 3, kc1 = s1 & 7;
            __half* Ad = Ab0 + (buf^1)*64*136;
            __half* Bd = Bb0 + (buf^1)*64*136;
            #pragma unroll
            for (int l = 0; l < 4; l++) {
                int idx = tid + l*256;
                int kr = idx >> 4, seg = idx & 15;
                cp16(&Ad[kr*136 + seg*8], g_Zh + (size_t)(p1*512 + kc1*64 + kr)*512 + rowBase + seg*8);
                cp16(&Bd[kr*136 + seg*8], g_xh + (size_t)(kc1*64 + kr)*NJ + colBase + seg*8);
            }
            cp_commit();
            cp_wait1();
        } else {
            cp_wait0();
        }
        __syncthreads();

        const __half* A = Ab0 + buf*64*136;
        const __half* B = Bb0 + buf*64*136;
        #pragma unroll
        for (int kk = 0; kk < 4; kk++) {
            int kb = kk*16;
            unsigned a[4][4], b[4][2];
            #pragma unroll
            for (int mf = 0; mf < 4; mf++)
                ldm4t(a[mf], A + (kb + aTrow)*136 + warpM + mf*16 + aTcol);
            #pragma unroll
            for (int nfp = 0; nfp < 2; nfp++) {
                unsigned r[4];
                ldm4t(r, B + (kb + bTrow)*136 + warpN + nfp*16 + bTcol);
                b[2*nfp][0] = r[0]; b[2*nfp][1] = r[1];
                b[2*nfp+1][0] = r[2]; b[2*nfp+1][1] = r[3];
            }
            #pragma unroll
            for (int mf = 0; mf < 4; mf++)
                #pragma unroll
                for (int nf = 0; nf < 4; nf++)
                    mma_f16(acc[mf][nf], a[mf], b[nf]);
        }
        __syncthreads();

        if (kc == 7) {
            int p = s >> 3;
            // acc -> Gs fp16, reset acc
            #pragma unroll
            for (int mf = 0; mf < 4; mf++)
                #pragma unroll
                for (int nf = 0; nf < 4; nf++) {
                    int r = warpM + mf*16 + qr, c = warpN + nf*8 + qc*2;
                    __half2 h0 = __floats2half2_rn(acc[mf][nf][0], acc[mf][nf][1]);
                    __half2 h1 = __floats2half2_rn(acc[mf][nf][2], acc[mf][nf][3]);
                    *(__half2*)&Gs[r*136 + c] = h0;
                    *(__half2*)&Gs[(r+8)*136 + c] = h1;
                    acc[mf][nf][0]=0.f; acc[mf][nf][1]=0.f; acc[mf][nf][2]=0.f; acc[mf][nf][3]=0.f;
                }
            __syncthreads();
            // GEMM2: oacc += Gs(bt-slice) @ Wh_p
            const int btoff = (warpN >> 6) * 64;
            const int obase = warpN & 63;
            const __half* Wp = Whs + p*4608;
            #pragma unroll
            for (int kk = 0; kk < 4; kk++) {
                int kb = kk*16;
                unsigned a[4][4], b[4][2];
                #pragma unroll
                for (int mf = 0; mf < 4; mf++)
                    ldm4(a[mf], Gs + (warpM + mf*16 + bTrow)*136 + btoff + kb + bTcol);
                #pragma unroll
                for (int nfp = 0; nfp < 2; nfp++) {
                    unsigned r[4];
                    ldm4t(r, Wp + (kb + bTrow)*72 + obase + nfp*16 + bTcol);
                    b[2*nfp][0] = r[0]; b[2*nfp][1] = r[1];
                    b[2*nfp+1][0] = r[2]; b[2*nfp+1][1] = r[3];
                }
                #pragma unroll
                for (int mf = 0; mf < 4; mf++)
                    #pragma unroll
                    for (int nf = 0; nf < 4; nf++)
                        mma_f16(oacc[mf][nf], a[mf], b[nf]);
            }
            __syncthreads();
        }
        buf ^= 1;
    }

    // identity piece: Gs = x_r tile, then GEMM2 with Wh[9]
    #pragma unroll
    for (int l = 0; l < 8; l++) {
        int idx = tid + l*256;
        int r = idx >> 4, seg = idx & 15;
        *(uint4*)&Gs[r*136 + seg*8] = *(const uint4*)(g_xh + (size_t)(rowBase + r)*NJ + colBase + seg*8);
    }
    __syncthreads();
    {
        const int btoff = (warpN >> 6) * 64;
        const int obase = warpN & 63;
        const __half* Wp = Whs + 9*4608;
        #pragma unroll
        for (int kk = 0; kk < 4; kk++) {
            int kb = kk*16;
            unsigned a[4][4], b[4][2];
            #pragma unroll
            for (int mf = 0; mf < 4; mf++)
                ldm4(a[mf], Gs + (warpM + mf*16 + bTrow)*136 + btoff + kb + bTcol);
            #pragma unroll
            for (int nfp = 0; nfp < 2; nfp++) {
                unsigned r[4];
                ldm4t(r, Wp + (kb + bTrow)*72 + obase + nfp*16 + bTcol);
                b[2*nfp][0] = r[0]; b[2*nfp][1] = r[1];
                b[2*nfp+1][0] = r[2]; b[2*nfp+1][1] = r[3];
            }
            #pragma unroll
            for (int mf = 0; mf < 4; mf++)
                #pragma unroll
                for (int nf = 0; nf < 4; nf++)
                    mma_f16(oacc[mf][nf], a[mf], b[nf]);
        }
    }
    __syncthreads();

    // epilogue: oacc -> Cs -> relu(+bias+x) -> out
    #pragma unroll
    for (int mf = 0; mf < 4; mf++)
        #pragma unroll
        for (int nf = 0; nf < 4; nf++) {
            int r = warpM + mf*16 + qr, c = warpN + nf*8 + qc*2;
            Cs[r*132 + c]     = oacc[mf][nf][0];
            Cs[r*132 + c + 1] = oacc[mf][nf][1];
            Cs[(r+8)*132 + c]     = oacc[mf][nf][2];
            Cs[(r+8)*132 + c + 1] = oacc[mf][nf][3];
        }
    __syncthreads();
    #pragma unroll
    for (int l = 0; l < 16; l++) {
        int idx = tid + l*256;            // 4096 quads
        int row = idx >> 5, nq = idx & 31;
        int col = colBase + nq*4;
        int o = col & 63, bt = col >> 6;
        int b = bt / 12, t = bt - b*12;
        int w = rowBase + row;
        size_t addr = ((size_t)((b*512 + w)*12 + t))*64 + o;
        float4 c  = *(float4*)&Cs[row*132 + nq*4];
        float4 bi = *(const float4*)(bias + o);
        float4 xr = *(const float4*)(x + addr);
        float4 r;
        r.x = fmaxf(c.x + bi.x + xr.x, 0.f);
        r.y = fmaxf(c.y + bi.y + xr.y, 0.f);
        r.z = fmaxf(c.z + bi.z + xr.z, 0.f);
        r.w = fmaxf(c.w + bi.w + xr.w, 0.f);
        *(float4*)(out + addr) = r;
    }
}

// ---------------- launch ----------------
extern "C" void kernel_launch(void* const* d_in, const int* in_sizes, int n_in,
                              void* d_out, int out_size) {
    (void)in_sizes; (void)n_in; (void)out_size;
    const float* x    = (const float*)d_in[0];
    const float* adj  = (const float*)d_in[1];
    const float* emb  = (const float*)d_in[2];
    const float* W1   = (const float*)d_in[3];
    const float* W2   = (const float*)d_in[4];
    const float* mlpw = (const float*)d_in[5];
    const float* mlpb = (const float*)d_in[6];
    float* out = (float*)d_out;

    float* za;
    cudaGetSymbolAddress((void**)&za, g_ZA);
    float* S[9];
    for (int p = 0; p < 9; p++) S[p] = za + (size_t)p * NN * NN;

    static int configured = 0;
    if (!configured) {
        cudaFuncSetAttribute(k_main, cudaFuncAttributeMaxDynamicSharedMemorySize, 196608);
        configured = 1;
    }

    k_softmax<<<1, 64>>>(W1, W2);
    k_embed<<<512, 64>>>(emb);
    k_buildA<<<512, 256>>>(adj);
    k_ls<<<512, 256>>>(S[0]);

    dim3 g8(8, 8);
    // slots: 0 Ls, 1 Ls^2, 2 Ls^3, 3 T2, 4 T2^2, 5 T2^3, 6 T3, 7 T3^2, 8 T3^3
    k_gemm512_tc<<<g8, 256>>>(S[0], S[0], S[3], 2.f, nullptr, -1.f, 1);   // T2
    k_gemm512_tc<<<g8, 256>>>(S[0], S[3], S[6], 2.f, S[0], -1.f, 0);      // T3
    k_gemm512_tc<<<g8, 256>>>(S[0], S[0], S[1], 1.f, nullptr, 0.f, 0);    // Ls^2
    k_gemm512_tc<<<g8, 256>>>(S[0], S[1], S[2], 1.f, nullptr, 0.f, 0);    // Ls^3
    k_gemm512_tc<<<g8, 256>>>(S[3], S[3], S[4], 1.f, nullptr, 0.f, 0);    // T2^2
    k_gemm512_tc<<<g8, 256>>>(S[3], S[4], S[5], 1.f, nullptr, 0.f, 0);    // T2^3
    k_gemm512_tc<<<g8, 256>>>(S[6], S[6], S[7], 1.f, nullptr, 0.f, 0);    // T3^2
    k_gemm512_tc<<<g8, 256>>>(S[6], S[7], S[8], 1.f, nullptr, 0.f, 0);    // T3^3

    k_zh<<<(NPIECE*NN*NN/4)/256, 256>>>(za);
    k_xh<<<dim3(32, 512), 192>>>(x);
    k_packWh<<<40, 1024>>>(mlpw);

    k_main<<<dim3(NJ/128, NN/128), 256, 196608>>>(x, mlpb, out);
}

// round 6
// speedup vs baseline: 5.7222x; 1.0888x over previous
#include <cuda_runtime.h>
#include <cuda_fp16.h>
#include <math.h>
#include <stdint.h>

#define NN 512
#define TT 12
#define NJ 24576
#define NNNN (NN*NN)

// ---------------- device scratch ----------------
__device__ float g_smW1[40*20];
__device__ float g_smW2[40*20];
__device__ float g_e1[NN*20];
__device__ float g_e2[NN*20];
__device__ float g_A[NN*NN];
__device__ float g_d[NN];
__device__ float g_P[(size_t)9*NNNN];            // powers Ls^1..Ls^9 (slot k-1), slot 7 unused
__device__ __align__(16) __half g_Zh[(size_t)10*NNNN]; // pieces fp16, [p][v][w]
__device__ __align__(16) __half g_xh[(size_t)NN*NJ];   // [v][(b*12+t)*64+c]
__device__ __align__(16) __half g_Wh[10*64*64];        // [p][c][o]

// power-product table: P_C = P_A @ P_B (slot indices)
__device__ const int POW_A[7] = {0,0,1,1,2,2,3};
__device__ const int POW_B[7] = {0,1,1,2,2,3,4};
__device__ const int POW_C[7] = {1,2,3,4,5,6,8};

// ---------------- helpers ----------------
__device__ __forceinline__ unsigned f2tf(float f) {
    unsigned u;
    asm("cvt.rna.tf32.f32 %0, %1;" : "=r"(u) : "f"(f));
    return u;
}
__device__ __forceinline__ void mma_tf32(float c[4], const unsigned a[4], const unsigned b[2]) {
    asm volatile("mma.sync.aligned.m16n8k8.row.col.f32.tf32.tf32.f32 "
        "{%0,%1,%2,%3}, {%4,%5,%6,%7}, {%8,%9}, {%0,%1,%2,%3};"
        : "+f"(c[0]), "+f"(c[1]), "+f"(c[2]), "+f"(c[3])
        : "r"(a[0]), "r"(a[1]), "r"(a[2]), "r"(a[3]), "r"(b[0]), "r"(b[1]));
}
__device__ __forceinline__ void mma_f16(float c[4], const unsigned a[4], const unsigned b[2]) {
    asm volatile("mma.sync.aligned.m16n8k16.row.col.f32.f16.f16.f32 "
        "{%0,%1,%2,%3}, {%4,%5,%6,%7}, {%8,%9}, {%0,%1,%2,%3};"
        : "+f"(c[0]), "+f"(c[1]), "+f"(c[2]), "+f"(c[3])
        : "r"(a[0]), "r"(a[1]), "r"(a[2]), "r"(a[3]), "r"(b[0]), "r"(b[1]));
}
__device__ __forceinline__ void ldm4t(unsigned r[4], const __half* p) {
    unsigned a = (unsigned)__cvta_generic_to_shared((void*)p);
    asm volatile("ldmatrix.sync.aligned.m8n8.x4.trans.shared.b16 {%0,%1,%2,%3}, [%4];"
        : "=r"(r[0]), "=r"(r[1]), "=r"(r[2]), "=r"(r[3]) : "r"(a));
}
__device__ __forceinline__ void ldm4(unsigned r[4], const __half* p) {
    unsigned a = (unsigned)__cvta_generic_to_shared((void*)p);
    asm volatile("ldmatrix.sync.aligned.m8n8.x4.shared.b16 {%0,%1,%2,%3}, [%4];"
        : "=r"(r[0]), "=r"(r[1]), "=r"(r[2]), "=r"(r[3]) : "r"(a));
}
__device__ __forceinline__ void cp16(const __half* smem_dst, const __half* gsrc) {
    unsigned sa = (unsigned)__cvta_generic_to_shared((void*)smem_dst);
    asm volatile("cp.async.ca.shared.global [%0], [%1], 16;" :: "r"(sa), "l"(gsrc));
}
__device__ __forceinline__ void cp_commit() { asm volatile("cp.async.commit_group;"); }
__device__ __forceinline__ void cp_wait0() { asm volatile("cp.async.wait_group 0;"); }
__device__ __forceinline__ void cp_wait1() { asm volatile("cp.async.wait_group 1;"); }

// ---------------- preprocessing ----------------
__global__ void k_softmax(const float* __restrict__ W1, const float* __restrict__ W2) {
    int t = threadIdx.x;
    if (t >= 40) return;
    const float* W = (t < 20) ? W1 : W2;
    float* S = (t < 20) ? g_smW1 : g_smW2;
    int c = (t < 20) ? t : t - 20;
    float m = -1e30f;
    for (int r = 0; r < 40; r++) m = fmaxf(m, W[r*20 + c]);
    float e[40];
    float s = 0.f;
    for (int r = 0; r < 40; r++) { e[r] = expf(W[r*20 + c] - m); s += e[r]; }
    float inv = 1.f / s;
    for (int r = 0; r < 40; r++) S[r*20 + c] = e[r] * inv;
}

__global__ void k_embed(const float* __restrict__ emb) {
    int i = blockIdx.x;
    __shared__ float es[40];
    __shared__ float r1[20], r2[20], nrm[2];
    int tid = threadIdx.x;
    if (tid < 40) es[tid] = emb[i*40 + tid];
    __syncthreads();
    if (tid < 20) {
        float s = 0.f;
        for (int q = 0; q < 40; q++) s += es[q] * g_smW1[q*20 + tid];
        r1[tid] = s;
    } else if (tid < 40) {
        int c = tid - 20;
        float s = 0.f;
        for (int q = 0; q < 40; q++) s += es[q] * g_smW2[q*20 + c];
        r2[c] = s;
    }
    __syncthreads();
    if (tid < 2) {
        const float* rr = tid ? r2 : r1;
        float s = 0.f;
        for (int q = 0; q < 20; q++) s += rr[q]*rr[q];
        nrm[tid] = sqrtf(s) + 1e-8f;
    }
    __syncthreads();
    if (tid < 20)      g_e1[i*20 + tid]       = r1[tid]      / nrm[0];
    else if (tid < 40) g_e2[i*20 + (tid-20)]  = r2[tid-20]   / nrm[1];
}

__global__ void k_buildA(const float* __restrict__ adj) {
    int i = blockIdx.x;
    __shared__ float e1s[20];
    __shared__ float red[256];
    int tid = threadIdx.x;
    if (tid < 20) e1s[tid] = g_e1[i*20 + tid];
    __syncthreads();
    float rs = 0.f;
    for (int j = tid; j < NN; j += 256) {
        float dot = 0.f;
        #pragma unroll
        for (int q = 0; q < 20; q++) dot += e1s[q] * g_e2[j*20 + q];
        float ad = adj[i*NN + j];
        float a = (ad > 0.f) ? (dot + ad) : 9e-15f;
        g_A[i*NN + j] = a;
        rs += a;
    }
    red[tid] = rs; __syncthreads();
    for (int s = 128; s > 0; s >>= 1) {
        if (tid < s) red[tid] += red[tid + s];
        __syncthreads();
    }
    if (tid == 0) g_d[i] = 1.f / sqrtf(red[0]);
}

// P1 = Ls
__global__ void k_ls() {
    int i = blockIdx.x;
    float di = g_d[i];
    for (int j = threadIdx.x; j < NN; j += 256)
        g_P[(size_t)i*NN + j] = -(di * g_A[i*NN + j] * g_d[j]);
}

// batched 512^3 tf32 gemm: P_C[z] = P_A[z] @ P_B[z]
__global__ void __launch_bounds__(256) k_pow(int base) {
    int z = base + blockIdx.z;
    const float* A = g_P + (size_t)POW_A[z]*NNNN;
    const float* B = g_P + (size_t)POW_B[z]*NNNN;
    float*       C = g_P + (size_t)POW_C[z]*NNNN;

    __shared__ unsigned As[64*36];
    __shared__ unsigned Bs[32*68];
    const int tid = threadIdx.x;
    const int wid = tid >> 5, lane = tid & 31;
    const int qr = lane >> 2, qc = lane & 3;
    const int warpM = (wid >> 2) * 32;
    const int warpN = (wid & 3) * 16;
    const int row0 = blockIdx.y * 64, col0 = blockIdx.x * 64;
    float acc[2][2][4] = {};
    for (int k0 = 0; k0 < 512; k0 += 32) {
        #pragma unroll
        for (int l = 0; l < 2; l++) {
            int idx = tid + l*256;
            int m = idx >> 3, k4 = (idx & 7) << 2;
            float4 v = *(const float4*)(A + (size_t)(row0 + m)*512 + k0 + k4);
            unsigned* d = &As[m*36 + k4];
            d[0]=f2tf(v.x); d[1]=f2tf(v.y); d[2]=f2tf(v.z); d[3]=f2tf(v.w);
        }
        #pragma unroll
        for (int l = 0; l < 2; l++) {
            int idx = tid + l*256;
            int kr = idx >> 4, n4 = (idx & 15) << 2;
            float4 v = *(const float4*)(B + (size_t)(k0 + kr)*512 + col0 + n4);
            unsigned* d = &Bs[kr*68 + n4];
            d[0]=f2tf(v.x); d[1]=f2tf(v.y); d[2]=f2tf(v.z); d[3]=f2tf(v.w);
        }
        __syncthreads();
        #pragma unroll
        for (int kk = 0; kk < 4; kk++) {
            int kb = kk*8;
            unsigned a[2][4], b[2][2];
            #pragma unroll
            for (int mf = 0; mf < 2; mf++) {
                int m = warpM + mf*16 + qr;
                a[mf][0] = As[m*36 + kb + qc];
                a[mf][1] = As[(m+8)*36 + kb + qc];
                a[mf][2] = As[m*36 + kb + qc + 4];
                a[mf][3] = As[(m+8)*36 + kb + qc + 4];
            }
            #pragma unroll
            for (int nf = 0; nf < 2; nf++) {
                int n = warpN + nf*8 + qr;
                b[nf][0] = Bs[(kb+qc)*68 + n];
                b[nf][1] = Bs[(kb+qc+4)*68 + n];
            }
            #pragma unroll
            for (int mf = 0; mf < 2; mf++)
                #pragma unroll
                for (int nf = 0; nf < 2; nf++)
                    mma_tf32(acc[mf][nf], a[mf], b[nf]);
        }
        __syncthreads();
    }
    #pragma unroll
    for (int mf = 0; mf < 2; mf++)
        #pragma unroll
        for (int nf = 0; nf < 2; nf++)
            #pragma unroll
            for (int e = 0; e < 4; e++) {
                int i = row0 + warpM + mf*16 + qr + (e >> 1)*8;
                int j = col0 + warpN + nf*8 + qc*2 + (e & 1);
                C[(size_t)i*512 + j] = acc[mf][nf][e];
            }
}

// build all 10 fp16 pieces from powers (elementwise, coalesced)
__global__ void k_combine() {
    int idx = blockIdx.x*256 + threadIdx.x;   // 65536 float4 groups
    size_t off = (size_t)idx*4;
    int v = (int)(off >> 9), w0 = (int)(off & 511);
    float4 q1 = *(const float4*)(g_P + 0*(size_t)NNNN + off);
    float4 q2 = *(const float4*)(g_P + 1*(size_t)NNNN + off);
    float4 q3 = *(const float4*)(g_P + 2*(size_t)NNNN + off);
    float4 q4 = *(const float4*)(g_P + 3*(size_t)NNNN + off);
    float4 q5 = *(const float4*)(g_P + 4*(size_t)NNNN + off);
    float4 q6 = *(const float4*)(g_P + 5*(size_t)NNNN + off);
    float4 q7 = *(const float4*)(g_P + 6*(size_t)NNNN + off);
    float4 q9 = *(const float4*)(g_P + 8*(size_t)NNNN + off);
    float P1[4] = {q1.x,q1.y,q1.z,q1.w};
    float P2[4] = {q2.x,q2.y,q2.z,q2.w};
    float P3[4] = {q3.x,q3.y,q3.z,q3.w};
    float P4[4] = {q4.x,q4.y,q4.z,q4.w};
    float P5[4] = {q5.x,q5.y,q5.z,q5.w};
    float P6[4] = {q6.x,q6.y,q6.z,q6.w};
    float P7[4] = {q7.x,q7.y,q7.z,q7.w};
    float P9[4] = {q9.x,q9.y,q9.z,q9.w};
    float Z[10][4];
    #pragma unroll
    for (int i = 0; i < 4; i++) {
        float D = (w0 + i == v) ? 1.f : 0.f;
        Z[0][i] = P1[i];
        Z[1][i] = P2[i];
        Z[2][i] = P3[i];
        Z[3][i] = 2.f*P2[i] - D;                                     // T2
        Z[4][i] = 4.f*P4[i] - 4.f*P2[i] + D;                         // T2^2
        Z[5][i] = 8.f*P6[i] - 12.f*P4[i] + 6.f*P2[i] - D;            // T2^3
        Z[6][i] = 4.f*P3[i] - 3.f*P1[i];                             // T3
        Z[7][i] = 16.f*P6[i] - 24.f*P4[i] + 9.f*P2[i];               // T3^2
        Z[8][i] = 64.f*P9[i] - 144.f*P7[i] + 108.f*P5[i] - 27.f*P3[i]; // T3^3
        Z[9][i] = D;
    }
    #pragma unroll
    for (int p = 0; p < 10; p++) {
        __half2 h0 = __floats2half2_rn(Z[p][0], Z[p][1]);
        __half2 h1 = __floats2half2_rn(Z[p][2], Z[p][3]);
        uint2 u; u.x = *(unsigned*)&h0; u.y = *(unsigned*)&h1;
        *(uint2*)(g_Zh + (size_t)p*NNNN + off) = u;
    }
}

// g_xh[v][(b*12+t)*64+c] = x[b][v][t][c]
__global__ void k_xh(const float* __restrict__ x) {
    int b = blockIdx.x, v = blockIdx.y;
    int tc = threadIdx.x * 4;
    float4 f = *(const float4*)(x + ((size_t)(b*512 + v)*12)*64 + tc);
    __half2 h0 = __floats2half2_rn(f.x, f.y), h1 = __floats2half2_rn(f.z, f.w);
    uint2 u; u.x = *(unsigned*)&h0; u.y = *(unsigned*)&h1;
    *(uint2*)(g_xh + (size_t)v*NJ + b*768 + tc) = u;
}

__global__ void k_packWh(const float* __restrict__ mlp_w) {
    int idx = blockIdx.x*1024 + threadIdx.x;   // 40960 total
    int p = idx >> 12, rem = idx & 4095;
    int c = rem >> 6, o = rem & 63;
    float v;
    if (p < 9) v = mlp_w[o*832 + 256 + p*64 + c];
    else       v = mlp_w[o*832 + c] + mlp_w[o*832 + 64 + c]
                 + mlp_w[o*832 + 128 + c] + mlp_w[o*832 + 192 + c];
    g_Wh[idx] = __float2half(v);
}

// ---------------- fused main kernel (512 threads, 16 warps) ----------------
__global__ void __launch_bounds__(512, 1) k_main(const float* __restrict__ x,
                                                 const float* __restrict__ bias,
                                                 float* __restrict__ out) {
    extern __shared__ __half sm[];
    __half* Ab0 = sm;                    // [64][136] x2
    __half* Bb0 = sm + 2*64*136;         // [64][136] x2
    __half* Gs  = sm + 4*64*136;         // [128][136]
    __half* Whs = Gs + 128*136;          // [10][64][72]
    float*  Cs  = (float*)sm;            // epilogue overlay (128x132 fp32)

    const int tid = threadIdx.x;
    const int wid = tid >> 5, lane = tid & 31;
    const int qr = lane >> 2, qc = lane & 3;
    const int warpM = (wid >> 2) * 32;        // 0,32,64,96
    const int warpN = (wid & 3) * 32;         // 0,32,64,96
    const int rowBase = blockIdx.y * 128;
    const int colBase = blockIdx.x * 128;

    const int g = lane >> 3, lrow = lane & 7;
    const int aTrow = (g >> 1)*8 + lrow, aTcol = (g & 1)*8;
    const int bTrow = (g & 1)*8 + lrow, bTcol = (g >> 1)*8;

    float acc[2][4][4] = {};
    float oacc[2][4][4] = {};

    // prefetch all W pieces
    #pragma unroll
    for (int l = 0; l < 10; l++) {
        int idx = tid + l*512;              // 5120 tasks
        int p = idx >> 9; int rem = idx & 511;
        int c = rem >> 3, seg = rem & 7;
        cp16(&Whs[p*4608 + c*72 + seg*8], g_Wh + (size_t)(p*64 + c)*64 + seg*8);
    }
    // prefetch stage 0 (p=0, kc=0)
    #pragma unroll
    for (int l = 0; l < 2; l++) {
        int idx = tid + l*512;
        int kr = idx >> 4, seg = idx & 15;
        cp16(&Ab0[kr*136 + seg*8], g_Zh + (size_t)kr*512 + rowBase + seg*8);
        cp16(&Bb0[kr*136 + seg*8], g_xh + (size_t)kr*NJ + colBase + seg*8);
    }
    cp_commit();

    int buf = 0;
    for (int s = 0; s < 72; s++) {
        int kc = s & 7;
        if (s < 71) {
            int s1 = s + 1;
            int p1 = s1 >> 3, kc1 = s1 & 7;
            __half* Ad = Ab0 + (buf^1)*64*136;
            __half* Bd = Bb0 + (buf^1)*64*136;
            #pragma unroll
            for (int l = 0; l < 2; l++) {
                int idx = tid + l*512;
                int kr = idx >> 4, seg = idx & 15;
                cp16(&Ad[kr*136 + seg*8], g_Zh + (size_t)(p1*512 + kc1*64 + kr)*512 + rowBase + seg*8);
                cp16(&Bd[kr*136 + seg*8], g_xh + (size_t)(kc1*64 + kr)*NJ + colBase + seg*8);
            }
            cp_commit();
            cp_wait1();
        } else {
            cp_wait0();
        }
        __syncthreads();

        const __half* A = Ab0 + buf*64*136;
        const __half* B = Bb0 + buf*64*136;
        #pragma unroll
        for (int kk = 0; kk < 4; kk++) {
            int kb = kk*16;
            unsigned a[2][4], b[4][2];
            #pragma unroll
            for (int mf = 0; mf < 2; mf++)
                ldm4t(a[mf], A + (kb + aTrow)*136 + warpM + mf*16 + aTcol);
            #pragma unroll
            for (int nfp = 0; nfp < 2; nfp++) {
                unsigned r[4];
                ldm4t(r, B + (kb + bTrow)*136 + warpN + nfp*16 + bTcol);
                b[2*nfp][0] = r[0]; b[2*nfp][1] = r[1];
                b[2*nfp+1][0] = r[2]; b[2*nfp+1][1] = r[3];
            }
            #pragma unroll
            for (int mf = 0; mf < 2; mf++)
                #pragma unroll
                for (int nf = 0; nf < 4; nf++)
                    mma_f16(acc[mf][nf], a[mf], b[nf]);
        }
        __syncthreads();

        if (kc == 7) {
            int p = s >> 3;
            // acc -> Gs fp16, reset acc
            #pragma unroll
            for (int mf = 0; mf < 2; mf++)
                #pragma unroll
                for (int nf = 0; nf < 4; nf++) {
                    int r = warpM + mf*16 + qr, c = warpN + nf*8 + qc*2;
                    __half2 h0 = __floats2half2_rn(acc[mf][nf][0], acc[mf][nf][1]);
                    __half2 h1 = __floats2half2_rn(acc[mf][nf][2], acc[mf][nf][3]);
                    *(__half2*)&Gs[r*136 + c] = h0;
                    *(__half2*)&Gs[(r+8)*136 + c] = h1;
                    acc[mf][nf][0]=0.f; acc[mf][nf][1]=0.f; acc[mf][nf][2]=0.f; acc[mf][nf][3]=0.f;
                }
            __syncthreads();
            // GEMM2: oacc += Gs(bt-slice) @ Wh_p
            const int btoff = warpN & 64;
            const int obase = warpN & 32;
            const __half* Wp = Whs + p*4608;
            #pragma unroll
            for (int kk = 0; kk < 4; kk++) {
                int kb = kk*16;
                unsigned a[2][4], b[4][2];
                #pragma unroll
                for (int mf = 0; mf < 2; mf++)
                    ldm4(a[mf], Gs + (warpM + mf*16 + bTrow)*136 + btoff + kb + bTcol);
                #pragma unroll
                for (int nfp = 0; nfp < 2; nfp++) {
                    unsigned r[4];
                    ldm4t(r, Wp + (kb + bTrow)*72 + obase + nfp*16 + bTcol);
                    b[2*nfp][0] = r[0]; b[2*nfp][1] = r[1];
                    b[2*nfp+1][0] = r[2]; b[2*nfp+1][1] = r[3];
                }
                #pragma unroll
                for (int mf = 0; mf < 2; mf++)
                    #pragma unroll
                    for (int nf = 0; nf < 4; nf++)
                        mma_f16(oacc[mf][nf], a[mf], b[nf]);
            }
            __syncthreads();
        }
        buf ^= 1;
    }

    // identity piece: Gs = x tile, then GEMM2 with Wh[9]
    #pragma unroll
    for (int l = 0; l < 4; l++) {
        int idx = tid + l*512;
        int r = idx >> 4, seg = idx & 15;
        *(uint4*)&Gs[r*136 + seg*8] = *(const uint4*)(g_xh + (size_t)(rowBase + r)*NJ + colBase + seg*8);
    }
    __syncthreads();
    {
        const int btoff = warpN & 64;
        const int obase = warpN & 32;
        const __half* Wp = Whs + 9*4608;
        #pragma unroll
        for (int kk = 0; kk < 4; kk++) {
            int kb = kk*16;
            unsigned a[2][4], b[4][2];
            #pragma unroll
            for (int mf = 0; mf < 2; mf++)
                ldm4(a[mf], Gs + (warpM + mf*16 + bTrow)*136 + btoff + kb + bTcol);
            #pragma unroll
            for (int nfp = 0; nfp < 2; nfp++) {
                unsigned r[4];
                ldm4t(r, Wp + (kb + bTrow)*72 + obase + nfp*16 + bTcol);
                b[2*nfp][0] = r[0]; b[2*nfp][1] = r[1];
                b[2*nfp+1][0] = r[2]; b[2*nfp+1][1] = r[3];
            }
            #pragma unroll
            for (int mf = 0; mf < 2; mf++)
                #pragma unroll
                for (int nf = 0; nf < 4; nf++)
                    mma_f16(oacc[mf][nf], a[mf], b[nf]);
        }
    }
    __syncthreads();

    // epilogue: oacc -> Cs -> relu(+bias+x) -> out
    #pragma unroll
    for (int mf = 0; mf < 2; mf++)
        #pragma unroll
        for (int nf = 0; nf < 4; nf++) {
            int r = warpM + mf*16 + qr, c = warpN + nf*8 + qc*2;
            Cs[r*132 + c]     = oacc[mf][nf][0];
            Cs[r*132 + c + 1] = oacc[mf][nf][1];
            Cs[(r+8)*132 + c]     = oacc[mf][nf][2];
            Cs[(r+8)*132 + c + 1] = oacc[mf][nf][3];
        }
    __syncthreads();
    #pragma unroll
    for (int l = 0; l < 8; l++) {
        int idx = tid + l*512;            // 4096 quads
        int row = idx >> 5, nq = idx & 31;
        int col = colBase + nq*4;
        int o = col & 63, bt = col >> 6;
        int b = bt / 12, t = bt - b*12;
        int w = rowBase + row;
        size_t addr = ((size_t)((b*512 + w)*12 + t))*64 + o;
        float4 c  = *(float4*)&Cs[row*132 + nq*4];
        float4 bi = *(const float4*)(bias + o);
        float4 xr = *(const float4*)(x + addr);
        float4 r;
        r.x = fmaxf(c.x + bi.x + xr.x, 0.f);
        r.y = fmaxf(c.y + bi.y + xr.y, 0.f);
        r.z = fmaxf(c.z + bi.z + xr.z, 0.f);
        r.w = fmaxf(c.w + bi.w + xr.w, 0.f);
        *(float4*)(out + addr) = r;
    }
}

// ---------------- launch ----------------
extern "C" void kernel_launch(void* const* d_in, const int* in_sizes, int n_in,
                              void* d_out, int out_size) {
    (void)in_sizes; (void)n_in; (void)out_size;
    const float* x    = (const float*)d_in[0];
    const float* adj  = (const float*)d_in[1];
    const float* emb  = (const float*)d_in[2];
    const float* W1   = (const float*)d_in[3];
    const float* W2   = (const float*)d_in[4];
    const float* mlpw = (const float*)d_in[5];
    const float* mlpb = (const float*)d_in[6];
    float* out = (float*)d_out;

    static int configured = 0;
    if (!configured) {
        cudaFuncSetAttribute(k_main, cudaFuncAttributeMaxDynamicSharedMemorySize, 196608);
        configured = 1;
    }

    k_softmax<<<1, 64>>>(W1, W2);
    k_embed<<<512, 64>>>(emb);
    k_buildA<<<512, 256>>>(adj);
    k_ls<<<512, 256>>>();

    // powers: P2 ; {P3,P4} ; {P5,P6,P7} ; P9
    k_pow<<<dim3(8, 8, 1), 256>>>(0);
    k_pow<<<dim3(8, 8, 2), 256>>>(1);
    k_pow<<<dim3(8, 8, 3), 256>>>(3);
    k_pow<<<dim3(8, 8, 1), 256>>>(6);
    k_combine<<<256, 256>>>();

    k_xh<<<dim3(32, 512), 192>>>(x);
    k_packWh<<<40, 1024>>>(mlpw);

    k_main<<<dim3(NJ/128, NN/128), 512, 196608>>>(x, mlpb, out);
}